// round 14
// baseline (speedup 1.0000x reference)
#include <cuda_runtime.h>

// conv2d 4096x4096 (fp32) * 15x15 VALID + bias -> 4082x4082 (fp32)
// R14: R12 (constant-port weights, FFMA2 phase-shifted dual accumulators,
//      4 blocks/SM) + cross-ky software pipeline: next row's head (P0..P7)
//      prefetched at c=3..6 with ping-pong registers, so no ky-boundary
//      LDS burst ever stalls the FMA stream.

#define H 4096
#define W 4096
#define KH 15
#define KW 15
#define OH 4082
#define OW 4082

#define BX 192          // 16 threads * RX=12
#define BY 16
#define NT 256
#define RX 12           // 48B lane stride: odd multiple of 16B -> conflict-free

#define IN_H (BY + KH - 1)          // 30
#define IN_HP 31                    // +1 pad row: final dead prefetch stays in bounds
#define SROW 208                    // pad 192+14 -> 208 (52 float4)

typedef unsigned long long ull;

__constant__ float cW[KH * KW];     // 225 floats, copied per launch (D2D memcpy node)

__device__ __forceinline__ ull pack2(float lo, float hi) {
    ull r; asm("mov.b64 %0, {%1, %2};" : "=l"(r) : "f"(lo), "f"(hi)); return r;
}
__device__ __forceinline__ void unpack2(ull v, float& lo, float& hi) {
    asm("mov.b64 {%0, %1}, %2;" : "=f"(lo), "=f"(hi) : "l"(v));
}
__device__ __forceinline__ ull fma2(ull a, ull b, ull c) {
    ull d; asm("fma.rn.f32x2 %0, %1, %2, %3;" : "=l"(d) : "l"(a), "l"(b), "l"(c)); return d;
}

// head = P0..P7 of a row (first 16 floats)
struct Head { ulonglong2 h[4]; };

// One ky step. cur head already resident; stages cur tail early (c=0..2),
// prefetches nxt head (c=3..6) for the following ky. Weights via const port.
__device__ __forceinline__ void ky_step(const Head& cur, Head& nxt,
                                        const float* rowCur, const float* rowNext,
                                        int wb,
                                        ull (&accA)[6], ull (&accB)[7]) {
    const ulonglong2* rc = (const ulonglong2*)rowCur;
    const ulonglong2* rn = (const ulonglong2*)rowNext;
    ulonglong2 v4, v5; ull v6;

    #pragma unroll
    for (int c = 0; c < 8; ++c) {
        if (c == 0) v4 = rc[4];                          // P8,P9   (first use c=2)
        if (c == 1) v5 = rc[5];                          // P10,P11 (first use c=4)
        if (c == 2) v6 = *(const ull*)(rowCur + 24);     // P12     (first use c=6)
        if (c == 3) nxt.h[0] = rn[0];                    // next ky head (use next c=0)
        if (c == 4) nxt.h[1] = rn[1];
        if (c == 5) nxt.h[2] = rn[2];
        if (c == 6) nxt.h[3] = rn[3];

        const float we = cW[wb + 2 * c];
        const ull wpx = pack2(we, we);
        #pragma unroll
        for (int j = 0; j < 6; ++j) {
            const int p = j + c;
            const ull Pp = (p < 8)  ? ((p & 1) ? cur.h[p >> 1].y : cur.h[p >> 1].x)
                         : (p == 8) ? v4.x : (p == 9) ? v4.y
                         : (p == 10) ? v5.x : (p == 11) ? v5.y : v6;
            accA[j] = fma2(wpx, Pp, accA[j]);
        }
        if (c < 7) {
            const float wo = cW[wb + 2 * c + 1];
            const ull wpy = pack2(wo, wo);
            #pragma unroll
            for (int j = 0; j < 7; ++j) {
                const int p = j + c;
                const ull Pp = (p < 8)  ? ((p & 1) ? cur.h[p >> 1].y : cur.h[p >> 1].x)
                             : (p == 8) ? v4.x : (p == 9) ? v4.y
                             : (p == 10) ? v5.x : (p == 11) ? v5.y : v6;
                accB[j] = fma2(wpy, Pp, accB[j]);
            }
        }
    }
}

__global__ __launch_bounds__(NT, 4)
void conv2d_r14_kernel(const float* __restrict__ X,
                       const float* __restrict__ bias,
                       float* __restrict__ out)
{
    __shared__ __align__(16) float sX[IN_HP][SROW];

    const int tid = threadIdx.x;
    const int bx = blockIdx.x * BX;
    const int by = blockIdx.y * BY;

    // ---- stage input tile: 30 rows x 208 cols, float4, guarded ----
    const int NV = IN_H * (SROW / 4);     // 30*52 = 1560 (pad row 30 unwritten)
    for (int idx = tid; idx < NV; idx += NT) {
        int r  = idx / (SROW / 4);
        int c4 = idx - r * (SROW / 4);
        int gr = by + r;
        int gc = bx + c4 * 4;
        float4 v = make_float4(0.f, 0.f, 0.f, 0.f);
        if (gr < H) {
            const float* src = X + (long)gr * W + gc;
            if (gc + 3 < W) v = *(const float4*)src;
            else {
                if (gc + 0 < W) v.x = src[0];
                if (gc + 1 < W) v.y = src[1];
                if (gc + 2 < W) v.z = src[2];
                if (gc + 3 < W) v.w = src[3];
            }
        }
        *(float4*)&sX[r][c4 * 4] = v;
    }
    __syncthreads();

    const int tx = tid & 15;
    const int ty = tid >> 4;
    const int ox = tx * RX;               // conflict-free, 16B aligned
    const float b0 = bias[0];

    ull accA[6];                          // (o_{2j}, o_{2j+1}); bias pre-folded
    ull accB[7];                          // (o_{2j-1}, o_{2j})
    {
        const ull bb = pack2(b0, b0);
        #pragma unroll
        for (int j = 0; j < 6; ++j) accA[j] = bb;
        #pragma unroll
        for (int j = 0; j < 7; ++j) accB[j] = 0ull;
    }

    Head A, B;
    {
        const ulonglong2* r0 = (const ulonglong2*)&sX[ty][ox];
        #pragma unroll
        for (int t = 0; t < 4; ++t) A.h[t] = r0[t];
    }

    const float* rowCur = &sX[ty][ox];
    int wb = 0;

    // 15 ky steps: 7 ping-pong pairs + final
    #pragma unroll 1
    for (int it = 0; it < 7; ++it) {
        ky_step(A, B, rowCur, rowCur + SROW, wb, accA, accB);
        rowCur += SROW; wb += KW;
        ky_step(B, A, rowCur, rowCur + SROW, wb, accA, accB);
        rowCur += SROW; wb += KW;
    }
    ky_step(A, B, rowCur, rowCur + SROW, wb, accA, accB);  // ky=14 (pad-row prefetch)

    // ---- epilogue: recombine phases, guarded float2 stores ----
    const int orow = by + ty;
    if (orow < OH) {
        float* orp = out + (long)orow * OW;
        float alo[6], ahi[6], blo[7], bhi[7];
        #pragma unroll
        for (int j = 0; j < 6; ++j) unpack2(accA[j], alo[j], ahi[j]);
        #pragma unroll
        for (int j = 0; j < 7; ++j) unpack2(accB[j], blo[j], bhi[j]);
        #pragma unroll
        for (int j = 0; j < 6; ++j) {
            int ocol = bx + ox + 2 * j;      // even; OW even -> pair fully in or out
            if (ocol < OW) {
                float2 st;
                st.x = alo[j] + bhi[j];          // o_{2j}   (bias in accA)
                st.y = ahi[j] + blo[j + 1];      // o_{2j+1}
                *(float2*)(orp + ocol) = st;
            }
        }
    }
}

extern "C" void kernel_launch(void* const* d_in, const int* in_sizes, int n_in,
                              void* d_out, int out_size)
{
    const float* X  = (const float*)d_in[0];
    const float* Wt = (const float*)d_in[1];
    const float* bs = (const float*)d_in[2];
    float* out = (float*)d_out;

    // weights -> constant bank (device-to-device async copy; graph-capturable)
    cudaMemcpyToSymbolAsync(cW, Wt, KH * KW * sizeof(float), 0,
                            cudaMemcpyDeviceToDevice, 0);

    dim3 grid((OW + BX - 1) / BX, (OH + BY - 1) / BY);   // 22 x 256
    conv2d_r14_kernel<<<grid, NT>>>(X, bs, out);
}

// round 15
// speedup vs baseline: 1.0762x; 1.0762x over previous
#include <cuda_runtime.h>

// conv2d 4096x4096 (fp32) * 15x15 VALID + bias -> 4082x4082 (fp32)
// R15: R12 operating point (constant-port weights, FFMA2 phase-shifted dual
//      accumulators, rolling staged window, 4-5 blocks/SM) with weights
//      pre-duplicated into (w,w) 64-bit pairs in __constant__ memory:
//      prep kernel -> __device__ scratch -> D2D memcpy to symbol.
//      Removes all 15 per-ky mov.b64 packs (alu pipe + issue slots).

#define H 4096
#define W 4096
#define KH 15
#define KW 15
#define OH 4082
#define OW 4082

#define BX 192          // 16 threads * RX=12
#define BY 16
#define NT 256
#define RX 12           // 48B lane stride: odd multiple of 16B -> conflict-free

#define IN_H (BY + KH - 1)          // 30
#define SROW 208                    // pad 192+14 -> 208 (52 float4)

typedef unsigned long long ull;

#define WP_N (KH * 16)              // 240 pairs (rows padded to 16)

__constant__ ull cW2[WP_N];         // (w,w) duplicated pairs
__device__ ull gWp[WP_N];           // scratch staging for the pairs

__device__ __forceinline__ ull pack2(float lo, float hi) {
    ull r; asm("mov.b64 %0, {%1, %2};" : "=l"(r) : "f"(lo), "f"(hi)); return r;
}
__device__ __forceinline__ void unpack2(ull v, float& lo, float& hi) {
    asm("mov.b64 {%0, %1}, %2;" : "=f"(lo), "=f"(hi) : "l"(v));
}
__device__ __forceinline__ ull fma2(ull a, ull b, ull c) {
    ull d; asm("fma.rn.f32x2 %0, %1, %2, %3;" : "=l"(d) : "l"(a), "l"(b), "l"(c)); return d;
}

// prep: expand 225 weights into 240 duplicated (w,w) pairs in gWp
__global__ void conv2d_r15_prep(const float* __restrict__ Wt)
{
    int idx = threadIdx.x;          // 256 threads, one pass
    if (idx < WP_N) {
        int r = idx >> 4, c = idx & 15;
        float w = (c < KW) ? Wt[r * KW + c] : 0.f;
        gWp[idx] = pack2(w, w);
    }
}

__global__ __launch_bounds__(NT, 4)
void conv2d_r15_kernel(const float* __restrict__ X,
                       const float* __restrict__ bias,
                       float* __restrict__ out)
{
    __shared__ __align__(16) float sX[IN_H][SROW];

    const int tid = threadIdx.x;
    const int bx = blockIdx.x * BX;
    const int by = blockIdx.y * BY;

    // ---- stage input tile: 30 rows x 208 cols, float4, guarded ----
    const int NV = IN_H * (SROW / 4);     // 30*52 = 1560
    for (int idx = tid; idx < NV; idx += NT) {
        int r  = idx / (SROW / 4);
        int c4 = idx - r * (SROW / 4);
        int gr = by + r;
        int gc = bx + c4 * 4;
        float4 v = make_float4(0.f, 0.f, 0.f, 0.f);
        if (gr < H) {
            const float* src = X + (long)gr * W + gc;
            if (gc + 3 < W) v = *(const float4*)src;
            else {
                if (gc + 0 < W) v.x = src[0];
                if (gc + 1 < W) v.y = src[1];
                if (gc + 2 < W) v.z = src[2];
                if (gc + 3 < W) v.w = src[3];
            }
        }
        *(float4*)&sX[r][c4 * 4] = v;
    }
    __syncthreads();

    const int tx = tid & 15;
    const int ty = tid >> 4;
    const int ox = tx * RX;               // conflict-free, 16B aligned
    const float b0 = bias[0];

    ull accA[6];                          // (o_{2j}, o_{2j+1}); bias pre-folded
    ull accB[7];                          // (o_{2j-1}, o_{2j})
    {
        const ull bb = pack2(b0, b0);
        #pragma unroll
        for (int j = 0; j < 6; ++j) accA[j] = bb;
        #pragma unroll
        for (int j = 0; j < 7; ++j) accB[j] = 0ull;
    }

    #pragma unroll 1
    for (int ky = 0; ky < KH; ++ky) {
        const ulonglong2* row = (const ulonglong2*)&sX[ty + ky][ox];
        const float* rowf = &sX[ty + ky][ox];
        const int wb = ky * 16;

        // rolling window with staging lead:
        // v[0..3] up front; v4@c=0 (use c=2), v5@c=1 (use c=4), v6@c=2 (use c=6)
        ulonglong2 v[6];
        ull v6;
        v[0] = row[0]; v[1] = row[1]; v[2] = row[2]; v[3] = row[3];

        #pragma unroll
        for (int c = 0; c < 8; ++c) {
            if (c == 0) v[4] = row[4];
            if (c == 1) v[5] = row[5];
            if (c == 2) v6 = *(const ull*)(rowf + 24);   // P12 (8B suffices)

            // duplicated weight pairs straight from the constant port (LDC.64)
            const ull wpx = cW2[wb + 2 * c];
            // even tap a=2c: accA[j] += w_{2c} * P[j+c], j=0..5
            #pragma unroll
            for (int j = 0; j < 6; ++j) {
                const int p = j + c;
                const ull Pp = (p == 12) ? v6 : ((p & 1) ? v[p >> 1].y : v[p >> 1].x);
                accA[j] = fma2(wpx, Pp, accA[j]);
            }
            // odd tap a=2c+1: accB[j] += w_{2c+1} * P[j+c], j=0..6
            if (c < 7) {
                const ull wpy = cW2[wb + 2 * c + 1];
                #pragma unroll
                for (int j = 0; j < 7; ++j) {
                    const int p = j + c;
                    const ull Pp = (p == 12) ? v6 : ((p & 1) ? v[p >> 1].y : v[p >> 1].x);
                    accB[j] = fma2(wpy, Pp, accB[j]);
                }
            }
        }
    }

    // ---- epilogue: recombine phases, guarded float2 stores ----
    const int orow = by + ty;
    if (orow < OH) {
        float* orp = out + (long)orow * OW;
        float alo[6], ahi[6], blo[7], bhi[7];
        #pragma unroll
        for (int j = 0; j < 6; ++j) unpack2(accA[j], alo[j], ahi[j]);
        #pragma unroll
        for (int j = 0; j < 7; ++j) unpack2(accB[j], blo[j], bhi[j]);
        #pragma unroll
        for (int j = 0; j < 6; ++j) {
            int ocol = bx + ox + 2 * j;      // even; OW even -> pair fully in or out
            if (ocol < OW) {
                float2 st;
                st.x = alo[j] + bhi[j];          // o_{2j}   (bias in accA)
                st.y = ahi[j] + blo[j + 1];      // o_{2j+1}
                *(float2*)(orp + ocol) = st;
            }
        }
    }
}

extern "C" void kernel_launch(void* const* d_in, const int* in_sizes, int n_in,
                              void* d_out, int out_size)
{
    const float* X  = (const float*)d_in[0];
    const float* Wt = (const float*)d_in[1];
    const float* bs = (const float*)d_in[2];
    float* out = (float*)d_out;

    // 1) expand weights into duplicated pairs in device scratch
    conv2d_r15_prep<<<1, 256>>>(Wt);

    // 2) move pairs into the constant bank (D2D memcpy node)
    void* gptr = nullptr;
    cudaGetSymbolAddress(&gptr, gWp);
    cudaMemcpyToSymbolAsync(cW2, gptr, WP_N * sizeof(ull), 0,
                            cudaMemcpyDeviceToDevice, 0);

    // 3) main conv
    dim3 grid((OW + BX - 1) / BX, (OH + BY - 1) / BY);   // 22 x 256
    conv2d_r15_kernel<<<grid, NT>>>(X, bs, out);
}